// round 6
// baseline (speedup 1.0000x reference)
#include <cuda_runtime.h>
#include <math.h>
#include <stdint.h>

// Problem constants
#define D_MODEL 1024
#define SEQ     2048
#define BATCH   2
#define HEADS   16
#define HEAD_DIM 64
#define MTOT (BATCH * SEQ)   // 4096 rows

// Scratch (device globals; no allocation allowed).
__device__ float g_Q[MTOT * D_MODEL];    // tf32, pre-scaled by 1/sqrt(D)
__device__ float g_K[MTOT * D_MODEL];    // tf32
__device__ float g_V[MTOT * D_MODEL];    // tf32
__device__ float g_O[MTOT * D_MODEL];    // tf32 (attn output)
__device__ float g_Xq[MTOT * D_MODEL];   // tf32 copy of queries
__device__ float g_Xk[MTOT * D_MODEL];
__device__ float g_Xv[MTOT * D_MODEL];
__device__ float g_Wqt[D_MODEL * D_MODEL];
__device__ float g_Wkt[D_MODEL * D_MODEL];
__device__ float g_Wvt[D_MODEL * D_MODEL];
__device__ float g_Wot[D_MODEL * D_MODEL];

__device__ __forceinline__ uint32_t f2tf32(float x) {
    uint32_t u;
    asm("cvt.rna.tf32.f32 %0, %1;" : "=r"(u) : "f"(x));
    return u;
}

__device__ __forceinline__ void mma_tf32(
    float& d0, float& d1, float& d2, float& d3,
    uint32_t a0, uint32_t a1, uint32_t a2, uint32_t a3,
    uint32_t b0, uint32_t b1)
{
    asm volatile(
        "mma.sync.aligned.m16n8k8.row.col.f32.tf32.tf32.f32 "
        "{%0,%1,%2,%3}, {%4,%5,%6,%7}, {%8,%9}, {%0,%1,%2,%3};\n"
        : "+f"(d0), "+f"(d1), "+f"(d2), "+f"(d3)
        : "r"(a0), "r"(a1), "r"(a2), "r"(a3), "r"(b0), "r"(b1));
}

__device__ __forceinline__ void cp16(uint32_t saddr, const float* g) {
    asm volatile("cp.async.cg.shared.global [%0], [%1], 16;\n"
                 :: "r"(saddr), "l"(g));
}
__device__ __forceinline__ void cp_commit() {
    asm volatile("cp.async.commit_group;\n");
}
template <int N>
__device__ __forceinline__ void cp_wait() {
    asm volatile("cp.async.wait_group %0;\n" :: "n"(N));
}

// ---------------------------------------------------------------------------
// Prep: rna tf32 conversion of inputs + weights.
// ---------------------------------------------------------------------------
__global__ __launch_bounds__(256) void prep_kernel(
    const float* __restrict__ q, const float* __restrict__ k,
    const float* __restrict__ v,
    const float* __restrict__ Wq, const float* __restrict__ Wk,
    const float* __restrict__ Wv, const float* __restrict__ Wo)
{
    const int z = blockIdx.y;
    const float* src;
    float* dst;
    int n4;
    switch (z) {
        case 0: src = q;  dst = g_Xq;  n4 = MTOT * D_MODEL / 4; break;
        case 1: src = k;  dst = g_Xk;  n4 = MTOT * D_MODEL / 4; break;
        case 2: src = v;  dst = g_Xv;  n4 = MTOT * D_MODEL / 4; break;
        case 3: src = Wq; dst = g_Wqt; n4 = D_MODEL * D_MODEL / 4; break;
        case 4: src = Wk; dst = g_Wkt; n4 = D_MODEL * D_MODEL / 4; break;
        case 5: src = Wv; dst = g_Wvt; n4 = D_MODEL * D_MODEL / 4; break;
        default:src = Wo; dst = g_Wot; n4 = D_MODEL * D_MODEL / 4; break;
    }
    const int i = blockIdx.x * 256 + threadIdx.x;
    if (i < n4) {
        float4 vld = reinterpret_cast<const float4*>(src)[i];
        uint4 u;
        u.x = f2tf32(vld.x); u.y = f2tf32(vld.y);
        u.z = f2tf32(vld.z); u.w = f2tf32(vld.w);
        reinterpret_cast<uint4*>(dst)[i] = u;
    }
}

// ---------------------------------------------------------------------------
// tf32 GEMM, fully cp.async (unchanged from R5).
// ---------------------------------------------------------------------------
#define BM 128
#define BN 128
#define BK 16
#define SA_ST 20
#define SB_ST 136
#define STAGES 4
#define AS_WORDS (BM * SA_ST)
#define BS_WORDS (BK * SB_ST)
#define AS_TOT (STAGES * AS_WORDS)
#define GEMM_SMEM ((AS_TOT + STAGES * BS_WORDS) * 4)

template <bool CVT>
__device__ __forceinline__ void gemm_body(
    const float* __restrict__ A, const float* __restrict__ W,
    const float* __restrict__ bias, float* __restrict__ C, float outScale)
{
    extern __shared__ uint32_t gsm[];
    const uint32_t su = (uint32_t)__cvta_generic_to_shared(gsm);

    const int tid  = threadIdx.x;
    const int warp = tid >> 5;
    const int lane = tid & 31;
    const int wm = (warp & 1) * 64;
    const int wn = (warp >> 1) * 32;
    const int rowBlk = blockIdx.y * BM;
    const int colBlk = blockIdx.x * BN;
    const int lr = lane >> 2;
    const int lc = lane & 3;

    const int ar0 = tid >> 2;
    const int ac0 = (tid & 3) << 2;
    const int bk0 = tid >> 5;
    const int bn0 = (tid & 31) << 2;

    auto issue = [&](int t, int s) {
        const uint32_t abase = su + (uint32_t)(s * AS_WORDS) * 4;
        const uint32_t bbase = su + (uint32_t)(AS_TOT + s * BS_WORDS) * 4;
        cp16(abase + (uint32_t)(ar0 * SA_ST + ac0) * 4,
             &A[(size_t)(rowBlk + ar0) * D_MODEL + t * BK + ac0]);
        cp16(abase + (uint32_t)((ar0 + 64) * SA_ST + ac0) * 4,
             &A[(size_t)(rowBlk + ar0 + 64) * D_MODEL + t * BK + ac0]);
        cp16(bbase + (uint32_t)(bk0 * SB_ST + bn0) * 4,
             &W[(size_t)(t * BK + bk0) * D_MODEL + colBlk + bn0]);
        cp16(bbase + (uint32_t)((bk0 + 8) * SB_ST + bn0) * 4,
             &W[(size_t)(t * BK + bk0 + 8) * D_MODEL + colBlk + bn0]);
        cp_commit();
    };

    float acc[4][4][4];
#pragma unroll
    for (int mi = 0; mi < 4; mi++)
#pragma unroll
        for (int ni = 0; ni < 4; ni++)
#pragma unroll
            for (int r = 0; r < 4; r++) acc[mi][ni][r] = 0.0f;

    issue(0, 0);
    issue(1, 1);
    issue(2, 2);

    const int NT = D_MODEL / BK;
    for (int t = 0; t < NT; t++) {
        cp_wait<2>();
        __syncthreads();
        if (t + 3 < NT) issue(t + 3, (t + 3) & (STAGES - 1));

        const int s = t & (STAGES - 1);
        const uint32_t* As = gsm + s * AS_WORDS;
        const uint32_t* Bs = gsm + AS_TOT + s * BS_WORDS;

#pragma unroll
        for (int ss = 0; ss < 2; ss++) {
            const int k0 = ss * 8;
            uint32_t af[4][4];
#pragma unroll
            for (int mi = 0; mi < 4; mi++) {
                const int m = wm + mi * 16 + lr;
                af[mi][0] = As[m * SA_ST + k0 + lc];
                af[mi][1] = As[(m + 8) * SA_ST + k0 + lc];
                af[mi][2] = As[m * SA_ST + k0 + lc + 4];
                af[mi][3] = As[(m + 8) * SA_ST + k0 + lc + 4];
            }
            uint32_t bf[4][2];
#pragma unroll
            for (int ni = 0; ni < 4; ni++) {
                const int n = wn + ni * 8 + lr;
                bf[ni][0] = Bs[(k0 + lc) * SB_ST + n];
                bf[ni][1] = Bs[(k0 + lc + 4) * SB_ST + n];
            }
#pragma unroll
            for (int mi = 0; mi < 4; mi++)
#pragma unroll
                for (int ni = 0; ni < 4; ni++)
                    mma_tf32(acc[mi][ni][0], acc[mi][ni][1],
                             acc[mi][ni][2], acc[mi][ni][3],
                             af[mi][0], af[mi][1], af[mi][2], af[mi][3],
                             bf[ni][0], bf[ni][1]);
        }
    }

#pragma unroll
    for (int mi = 0; mi < 4; mi++) {
        const int row0 = rowBlk + wm + mi * 16 + lr;
#pragma unroll
        for (int ni = 0; ni < 4; ni++) {
            const int col = colBlk + wn + ni * 8 + lc * 2;
            const float2 bb = *reinterpret_cast<const float2*>(&bias[col]);
            float v00 = (acc[mi][ni][0] + bb.x) * outScale;
            float v01 = (acc[mi][ni][1] + bb.y) * outScale;
            float v10 = (acc[mi][ni][2] + bb.x) * outScale;
            float v11 = (acc[mi][ni][3] + bb.y) * outScale;
            if (CVT) {
                uint2 u0, u1;
                u0.x = f2tf32(v00); u0.y = f2tf32(v01);
                u1.x = f2tf32(v10); u1.y = f2tf32(v11);
                *reinterpret_cast<uint2*>(&C[(size_t)row0 * D_MODEL + col]) = u0;
                *reinterpret_cast<uint2*>(&C[(size_t)(row0 + 8) * D_MODEL + col]) = u1;
            } else {
                float2 o0, o1;
                o0.x = v00; o0.y = v01;
                o1.x = v10; o1.y = v11;
                *reinterpret_cast<float2*>(&C[(size_t)row0 * D_MODEL + col]) = o0;
                *reinterpret_cast<float2*>(&C[(size_t)(row0 + 8) * D_MODEL + col]) = o1;
            }
        }
    }
}

__global__ __launch_bounds__(256, 2) void qkv_gemm_kernel_b(
    const float* __restrict__ bq, const float* __restrict__ bk,
    const float* __restrict__ bv)
{
    const int z = blockIdx.z;
    const float* A = (z == 0) ? g_Xq : (z == 1) ? g_Xk : g_Xv;
    const float* W = (z == 0) ? g_Wqt : (z == 1) ? g_Wkt : g_Wvt;
    const float* b = (z == 0) ? bq : (z == 1) ? bk : bv;
    float*       C = (z == 0) ? g_Q : (z == 1) ? g_K : g_V;
    const float sc = (z == 0) ? 0.03125f : 1.0f;
    gemm_body<true>(A, W, b, C, sc);
}

__global__ __launch_bounds__(256, 2) void gemm_o_kernel(
    const float* __restrict__ bias, float* __restrict__ C)
{
    gemm_body<false>(g_O, g_Wot, bias, C, 1.0f);
}

// ---------------------------------------------------------------------------
// tf32 flash attention, 2 CTAs/SM version.
// Q persistent in smem [128][68]; K chunks of 32 keys, 3-stage cp.async;
// P [128][36]. All gathers keep the proven (4*lr+lc) / (8*lc+lr) conflict-
// free bank patterns (strides 68,36 == 4 mod 32; 72 == 8 mod 32).
// ---------------------------------------------------------------------------
#define QTILE 128
#define KCH 32
#define KST 68
#define VST 72
#define PST 36
#define QW (QTILE * KST)            // 8704 words
#define KW (KCH * KST)              // 2176
#define VW (KCH * VST)              // 2304
#define OFF_K QW
#define OFF_V (QW + 3 * KW)
#define OFF_P (QW + 3 * KW + 3 * VW)
#define ATTN_WORDS (OFF_P + QTILE * PST)
#define ATTN_SMEM (ATTN_WORDS * 4)  // (8704+6528+6912+4608)*4 = 107008 B
#define NTC (SEQ / KCH)             // 64

__global__ __launch_bounds__(256, 2) void attn_kernel()
{
    extern __shared__ uint32_t smu[];
    const uint32_t su = (uint32_t)__cvta_generic_to_shared(smu);
    uint32_t* Qsm = smu;
    uint32_t* Psm = smu + OFF_P;

    const int tid  = threadIdx.x;
    const int warp = tid >> 5;
    const int lane = tid & 31;
    const int lr = lane >> 2;
    const int lc = lane & 3;
    const int wm = warp * 16;

    const int qblk = blockIdx.x;
    const int bh   = blockIdx.y;
    const int b = bh >> 4;
    const int h = bh & 15;
    const size_t baseRow = (size_t)b * SEQ;
    const int colOff = h * HEAD_DIM;

    // per-thread chunk-copy coords: 512 x 16B per chunk (K) + 512 (V)
    const int cr0 = tid >> 4;              // 0..15 (rows tid>>4 and +16)
    const int cd4 = (tid & 15) << 2;

    auto issue_chunk = [&](int kt, int s) {
        const uint32_t kb = su + (uint32_t)(OFF_K + s * KW) * 4;
        const uint32_t vb = su + (uint32_t)(OFF_V + s * VW) * 4;
#pragma unroll
        for (int i = 0; i < 2; i++) {
            const int r = cr0 + 16 * i;
            const size_t g = (baseRow + (size_t)kt * KCH + r) * D_MODEL + colOff + cd4;
            cp16(kb + (uint32_t)(r * KST + cd4) * 4, &g_K[g]);
            cp16(vb + (uint32_t)(r * VST + cd4) * 4, &g_V[g]);
        }
        cp_commit();
    };

    issue_chunk(0, 0);
    issue_chunk(1, 1);

    // stage Q (raw tf32, already scaled) into persistent Qsm
#pragma unroll
    for (int i = 0; i < 8; i++) {
        const int idx = tid + 256 * i;
        const int r  = idx >> 4;
        const int d4 = (idx & 15) << 2;
        *reinterpret_cast<uint4*>(&Qsm[r * KST + d4]) =
            *reinterpret_cast<const uint4*>(
                &g_Q[(baseRow + qblk * QTILE + r) * D_MODEL + colOff + d4]);
    }

    float oacc[8][4];
#pragma unroll
    for (int ni = 0; ni < 8; ni++)
#pragma unroll
        for (int r = 0; r < 4; r++) oacc[ni][r] = 0.0f;
    float m0 = -INFINITY, m1 = -INFINITY, l0 = 0.0f, l1 = 0.0f;

    int s = 0;        // buffer of current chunk
    int sn = 2;       // buffer for prefetch (kt+2)
    __syncthreads();  // Q staging visible before first compute

    for (int kt = 0; kt < NTC; kt++) {
        if (kt + 2 < NTC) {
            issue_chunk(kt + 2, sn);
            cp_wait<2>();
        } else if (kt + 1 < NTC) {
            cp_wait<1>();
        } else {
            cp_wait<0>();
        }
        __syncthreads();   // chunk kt visible to all warps

        const uint32_t* Ksm = smu + OFF_K + s * KW;
        const uint32_t* Vsm = smu + OFF_V + s * VW;

        // ---- S = Q @ K^T : 16 rows x 32 keys per warp ----
        float sacc[4][4];
#pragma unroll
        for (int ni = 0; ni < 4; ni++)
#pragma unroll
            for (int r = 0; r < 4; r++) sacc[ni][r] = 0.0f;
#pragma unroll
        for (int ks = 0; ks < 8; ks++) {
            const int k0 = ks * 8;
            const uint32_t a0 = Qsm[(wm + lr    ) * KST + k0 + lc    ];
            const uint32_t a1 = Qsm[(wm + lr + 8) * KST + k0 + lc    ];
            const uint32_t a2 = Qsm[(wm + lr    ) * KST + k0 + lc + 4];
            const uint32_t a3 = Qsm[(wm + lr + 8) * KST + k0 + lc + 4];
#pragma unroll
            for (int ni = 0; ni < 4; ni++) {
                const uint32_t b0 = Ksm[(ni * 8 + lr) * KST + k0 + lc    ];
                const uint32_t b1 = Ksm[(ni * 8 + lr) * KST + k0 + lc + 4];
                mma_tf32(sacc[ni][0], sacc[ni][1], sacc[ni][2], sacc[ni][3],
                         a0, a1, a2, a3, b0, b1);
            }
        }

        // ---- online softmax (warp-local, 4 lanes/row via xor 1,2) ----
        float lm0 = -INFINITY, lm1 = -INFINITY;
#pragma unroll
        for (int ni = 0; ni < 4; ni++) {
            lm0 = fmaxf(lm0, fmaxf(sacc[ni][0], sacc[ni][1]));
            lm1 = fmaxf(lm1, fmaxf(sacc[ni][2], sacc[ni][3]));
        }
        lm0 = fmaxf(lm0, __shfl_xor_sync(0xffffffffu, lm0, 1));
        lm0 = fmaxf(lm0, __shfl_xor_sync(0xffffffffu, lm0, 2));
        lm1 = fmaxf(lm1, __shfl_xor_sync(0xffffffffu, lm1, 1));
        lm1 = fmaxf(lm1, __shfl_xor_sync(0xffffffffu, lm1, 2));
        const float mn0 = fmaxf(m0, lm0);
        const float mn1 = fmaxf(m1, lm1);
        const float a0s = __expf(m0 - mn0);
        const float a1s = __expf(m1 - mn1);
        m0 = mn0; m1 = mn1;
        float rs0 = 0.0f, rs1 = 0.0f;
#pragma unroll
        for (int ni = 0; ni < 4; ni++) {
            sacc[ni][0] = __expf(sacc[ni][0] - mn0);
            sacc[ni][1] = __expf(sacc[ni][1] - mn0);
            sacc[ni][2] = __expf(sacc[ni][2] - mn1);
            sacc[ni][3] = __expf(sacc[ni][3] - mn1);
            rs0 += sacc[ni][0] + sacc[ni][1];
            rs1 += sacc[ni][2] + sacc[ni][3];
        }
        rs0 += __shfl_xor_sync(0xffffffffu, rs0, 1);
        rs0 += __shfl_xor_sync(0xffffffffu, rs0, 2);
        rs1 += __shfl_xor_sync(0xffffffffu, rs1, 1);
        rs1 += __shfl_xor_sync(0xffffffffu, rs1, 2);
        l0 = l0 * a0s + rs0;
        l1 = l1 * a1s + rs1;
#pragma unroll
        for (int ni = 0; ni < 8; ni++) {
            oacc[ni][0] *= a0s; oacc[ni][1] *= a0s;
            oacc[ni][2] *= a1s; oacc[ni][3] *= a1s;
        }

        // ---- write P (tf32) to smem (warp-private rows) ----
#pragma unroll
        for (int ni = 0; ni < 4; ni++) {
            const int col = ni * 8 + lc * 2;
            uint2 p0, p1;
            p0.x = f2tf32(sacc[ni][0]); p0.y = f2tf32(sacc[ni][1]);
            p1.x = f2tf32(sacc[ni][2]); p1.y = f2tf32(sacc[ni][3]);
            *reinterpret_cast<uint2*>(&Psm[(wm + lr    ) * PST + col]) = p0;
            *reinterpret_cast<uint2*>(&Psm[(wm + lr + 8) * PST + col]) = p1;
        }
        __syncwarp();

        // ---- O += P @ V  (k-dim = 32 keys) ----
#pragma unroll
        for (int ks = 0; ks < 4; ks++) {
            const int k0 = ks * 8;
            const uint32_t af0 = Psm[(wm + lr    ) * PST + k0 + lc    ];
            const uint32_t af1 = Psm[(wm + lr + 8) * PST + k0 + lc    ];
            const uint32_t af2 = Psm[(wm + lr    ) * PST + k0 + lc + 4];
            const uint32_t af3 = Psm[(wm + lr + 8) * PST + k0 + lc + 4];
#pragma unroll
            for (int ni = 0; ni < 8; ni++) {
                const uint32_t b0 = Vsm[(k0 + lc    ) * VST + ni * 8 + lr];
                const uint32_t b1 = Vsm[(k0 + lc + 4) * VST + ni * 8 + lr];
                mma_tf32(oacc[ni][0], oacc[ni][1], oacc[ni][2], oacc[ni][3],
                         af0, af1, af2, af3, b0, b1);
            }
        }
        __syncthreads();   // chunk buffer consumed; safe to refill

        s  = (s  == 2) ? 0 : s + 1;
        sn = (sn == 2) ? 0 : sn + 1;
    }

    // ---- normalize, cvt tf32, store for O-GEMM ----
    const float inv0 = 1.0f / l0;
    const float inv1 = 1.0f / l1;
    const size_t r0 = baseRow + qblk * QTILE + wm + lr;
    uint32_t* Og = reinterpret_cast<uint32_t*>(g_O);
#pragma unroll
    for (int ni = 0; ni < 8; ni++) {
        const int col = colOff + ni * 8 + lc * 2;
        uint2 o0, o1;
        o0.x = f2tf32(oacc[ni][0] * inv0); o0.y = f2tf32(oacc[ni][1] * inv0);
        o1.x = f2tf32(oacc[ni][2] * inv1); o1.y = f2tf32(oacc[ni][3] * inv1);
        *reinterpret_cast<uint2*>(&Og[r0 * D_MODEL + col]) = o0;
        *reinterpret_cast<uint2*>(&Og[(r0 + 8) * D_MODEL + col]) = o1;
    }
}

// ---------------------------------------------------------------------------
extern "C" void kernel_launch(void* const* d_in, const int* in_sizes, int n_in,
                              void* d_out, int out_size)
{
    const float* queries = (const float*)d_in[0];
    const float* keys    = (const float*)d_in[1];
    const float* values  = (const float*)d_in[2];
    const float* Wq = (const float*)d_in[3];
    const float* bq = (const float*)d_in[4];
    const float* Wk = (const float*)d_in[5];
    const float* bk = (const float*)d_in[6];
    const float* Wv = (const float*)d_in[7];
    const float* bv = (const float*)d_in[8];
    const float* Wo = (const float*)d_in[9];
    const float* bo = (const float*)d_in[10];
    float* out = (float*)d_out;

    prep_kernel<<<dim3(MTOT * D_MODEL / 4 / 256, 7), 256>>>(
        queries, keys, values, Wq, Wk, Wv, Wo);

    cudaFuncSetAttribute(qkv_gemm_kernel_b,
                         cudaFuncAttributeMaxDynamicSharedMemorySize, GEMM_SMEM);
    cudaFuncSetAttribute(gemm_o_kernel,
                         cudaFuncAttributeMaxDynamicSharedMemorySize, GEMM_SMEM);
    cudaFuncSetAttribute(attn_kernel,
                         cudaFuncAttributeMaxDynamicSharedMemorySize, ATTN_SMEM);

    qkv_gemm_kernel_b<<<dim3(D_MODEL / BN, MTOT / BM, 3), 256, GEMM_SMEM>>>(
        bq, bk, bv);

    attn_kernel<<<dim3(SEQ / QTILE, BATCH * HEADS), 256, ATTN_SMEM>>>();

    gemm_o_kernel<<<dim3(D_MODEL / BN, MTOT / BM), 256, GEMM_SMEM>>>(bo, out);
}

// round 7
// speedup vs baseline: 1.1142x; 1.1142x over previous
#include <cuda_runtime.h>
#include <math.h>
#include <stdint.h>

// Problem constants
#define D_MODEL 1024
#define SEQ     2048
#define BATCH   2
#define HEADS   16
#define HEAD_DIM 64
#define MTOT (BATCH * SEQ)   // 4096 rows

// Scratch (device globals; no allocation allowed).
__device__ float g_Q[MTOT * D_MODEL];    // tf32, pre-scaled by 1/sqrt(D)
__device__ float g_K[MTOT * D_MODEL];    // tf32
__device__ float g_V[MTOT * D_MODEL];    // tf32
__device__ float g_O[MTOT * D_MODEL];    // tf32 (attn output)
__device__ float g_Xq[MTOT * D_MODEL];   // tf32 copy of queries
__device__ float g_Xk[MTOT * D_MODEL];
__device__ float g_Xv[MTOT * D_MODEL];
__device__ float g_Wqt[D_MODEL * D_MODEL];
__device__ float g_Wkt[D_MODEL * D_MODEL];
__device__ float g_Wvt[D_MODEL * D_MODEL];
__device__ float g_Wot[D_MODEL * D_MODEL];

__device__ __forceinline__ uint32_t f2tf32(float x) {
    uint32_t u;
    asm("cvt.rna.tf32.f32 %0, %1;" : "=r"(u) : "f"(x));
    return u;
}

__device__ __forceinline__ void mma_tf32(
    float& d0, float& d1, float& d2, float& d3,
    uint32_t a0, uint32_t a1, uint32_t a2, uint32_t a3,
    uint32_t b0, uint32_t b1)
{
    asm volatile(
        "mma.sync.aligned.m16n8k8.row.col.f32.tf32.tf32.f32 "
        "{%0,%1,%2,%3}, {%4,%5,%6,%7}, {%8,%9}, {%0,%1,%2,%3};\n"
        : "+f"(d0), "+f"(d1), "+f"(d2), "+f"(d3)
        : "r"(a0), "r"(a1), "r"(a2), "r"(a3), "r"(b0), "r"(b1));
}

__device__ __forceinline__ void cp16(uint32_t saddr, const float* g) {
    asm volatile("cp.async.cg.shared.global [%0], [%1], 16;\n"
                 :: "r"(saddr), "l"(g));
}
__device__ __forceinline__ void cp_commit() {
    asm volatile("cp.async.commit_group;\n");
}
template <int N>
__device__ __forceinline__ void cp_wait() {
    asm volatile("cp.async.wait_group %0;\n" :: "n"(N));
}

// ---------------------------------------------------------------------------
// Prep: rna tf32 conversion of inputs + weights.
// ---------------------------------------------------------------------------
__global__ __launch_bounds__(256) void prep_kernel(
    const float* __restrict__ q, const float* __restrict__ k,
    const float* __restrict__ v,
    const float* __restrict__ Wq, const float* __restrict__ Wk,
    const float* __restrict__ Wv, const float* __restrict__ Wo)
{
    const int z = blockIdx.y;
    const float* src;
    float* dst;
    int n4;
    switch (z) {
        case 0: src = q;  dst = g_Xq;  n4 = MTOT * D_MODEL / 4; break;
        case 1: src = k;  dst = g_Xk;  n4 = MTOT * D_MODEL / 4; break;
        case 2: src = v;  dst = g_Xv;  n4 = MTOT * D_MODEL / 4; break;
        case 3: src = Wq; dst = g_Wqt; n4 = D_MODEL * D_MODEL / 4; break;
        case 4: src = Wk; dst = g_Wkt; n4 = D_MODEL * D_MODEL / 4; break;
        case 5: src = Wv; dst = g_Wvt; n4 = D_MODEL * D_MODEL / 4; break;
        default:src = Wo; dst = g_Wot; n4 = D_MODEL * D_MODEL / 4; break;
    }
    const int i = blockIdx.x * 256 + threadIdx.x;
    if (i < n4) {
        float4 vld = reinterpret_cast<const float4*>(src)[i];
        uint4 u;
        u.x = f2tf32(vld.x); u.y = f2tf32(vld.y);
        u.z = f2tf32(vld.z); u.w = f2tf32(vld.w);
        reinterpret_cast<uint4*>(dst)[i] = u;
    }
}

// ---------------------------------------------------------------------------
// tf32 GEMM, fully cp.async. BK=32, 3-stage pipeline (32 iterations, half
// the barriers of the BK=16 version). A smem m-major stride 36 (== 4 mod 32,
// same conflict-free gather as stride 68); B k-major stride 136.
// Accumulation order over k unchanged -> bit-identical results.
// ---------------------------------------------------------------------------
#define BM 128
#define BN 128
#define BK 32
#define SA_ST 36
#define SB_ST 136
#define STAGES 3
#define AS_WORDS (BM * SA_ST)            // 4608
#define BS_WORDS (BK * SB_ST)            // 4352
#define AS_TOT (STAGES * AS_WORDS)       // 13824
#define GEMM_SMEM ((AS_TOT + STAGES * BS_WORDS) * 4)   // 107520 B

template <bool CVT>
__device__ __forceinline__ void gemm_body(
    const float* __restrict__ A, const float* __restrict__ W,
    const float* __restrict__ bias, float* __restrict__ C, float outScale)
{
    extern __shared__ uint32_t gsm[];
    const uint32_t su = (uint32_t)__cvta_generic_to_shared(gsm);

    const int tid  = threadIdx.x;
    const int warp = tid >> 5;
    const int lane = tid & 31;
    const int wm = (warp & 1) * 64;
    const int wn = (warp >> 1) * 32;
    const int rowBlk = blockIdx.y * BM;
    const int colBlk = blockIdx.x * BN;
    const int lr = lane >> 2;
    const int lc = lane & 3;

    // copy coords: A tile 128x32 = 1024 16B-chunks, B tile 32x128 = 1024.
    // 4 chunks each per thread.
    const int ar = tid >> 3;               // row for idx=tid (+32 per i)
    const int ac4 = (tid & 7) << 2;
    const int bk = tid >> 5;               // k for idx=tid (+8 per i)
    const int bn4 = (tid & 31) << 2;

    auto issue = [&](int t, int s) {
        const uint32_t abase = su + (uint32_t)(s * AS_WORDS) * 4;
        const uint32_t bbase = su + (uint32_t)(AS_TOT + s * BS_WORDS) * 4;
#pragma unroll
        for (int i = 0; i < 4; i++) {
            const int r = ar + 32 * i;
            cp16(abase + (uint32_t)(r * SA_ST + ac4) * 4,
                 &A[(size_t)(rowBlk + r) * D_MODEL + t * BK + ac4]);
        }
#pragma unroll
        for (int i = 0; i < 4; i++) {
            const int kk = bk + 8 * i;
            cp16(bbase + (uint32_t)(kk * SB_ST + bn4) * 4,
                 &W[(size_t)(t * BK + kk) * D_MODEL + colBlk + bn4]);
        }
        cp_commit();
    };

    float acc[4][4][4];
#pragma unroll
    for (int mi = 0; mi < 4; mi++)
#pragma unroll
        for (int ni = 0; ni < 4; ni++)
#pragma unroll
            for (int r = 0; r < 4; r++) acc[mi][ni][r] = 0.0f;

    issue(0, 0);
    issue(1, 1);

    const int NT = D_MODEL / BK;   // 32
    for (int t = 0; t < NT; t++) {
        if (t + 1 < NT) cp_wait<1>(); else cp_wait<0>();
        __syncthreads();
        if (t + 2 < NT) issue(t + 2, (t + 2) % STAGES);

        const int s = t % STAGES;
        const uint32_t* As = gsm + s * AS_WORDS;
        const uint32_t* Bs = gsm + AS_TOT + s * BS_WORDS;

#pragma unroll
        for (int ss = 0; ss < 4; ss++) {
            const int k0 = ss * 8;
            uint32_t af[4][4];
#pragma unroll
            for (int mi = 0; mi < 4; mi++) {
                const int m = wm + mi * 16 + lr;
                af[mi][0] = As[m * SA_ST + k0 + lc];
                af[mi][1] = As[(m + 8) * SA_ST + k0 + lc];
                af[mi][2] = As[m * SA_ST + k0 + lc + 4];
                af[mi][3] = As[(m + 8) * SA_ST + k0 + lc + 4];
            }
            uint32_t bf[4][2];
#pragma unroll
            for (int ni = 0; ni < 4; ni++) {
                const int n = wn + ni * 8 + lr;
                bf[ni][0] = Bs[(k0 + lc) * SB_ST + n];
                bf[ni][1] = Bs[(k0 + lc + 4) * SB_ST + n];
            }
#pragma unroll
            for (int mi = 0; mi < 4; mi++)
#pragma unroll
                for (int ni = 0; ni < 4; ni++)
                    mma_tf32(acc[mi][ni][0], acc[mi][ni][1],
                             acc[mi][ni][2], acc[mi][ni][3],
                             af[mi][0], af[mi][1], af[mi][2], af[mi][3],
                             bf[ni][0], bf[ni][1]);
        }
    }

#pragma unroll
    for (int mi = 0; mi < 4; mi++) {
        const int row0 = rowBlk + wm + mi * 16 + lr;
#pragma unroll
        for (int ni = 0; ni < 4; ni++) {
            const int col = colBlk + wn + ni * 8 + lc * 2;
            const float2 bb = *reinterpret_cast<const float2*>(&bias[col]);
            float v00 = (acc[mi][ni][0] + bb.x) * outScale;
            float v01 = (acc[mi][ni][1] + bb.y) * outScale;
            float v10 = (acc[mi][ni][2] + bb.x) * outScale;
            float v11 = (acc[mi][ni][3] + bb.y) * outScale;
            if (CVT) {
                uint2 u0, u1;
                u0.x = f2tf32(v00); u0.y = f2tf32(v01);
                u1.x = f2tf32(v10); u1.y = f2tf32(v11);
                *reinterpret_cast<uint2*>(&C[(size_t)row0 * D_MODEL + col]) = u0;
                *reinterpret_cast<uint2*>(&C[(size_t)(row0 + 8) * D_MODEL + col]) = u1;
            } else {
                float2 o0, o1;
                o0.x = v00; o0.y = v01;
                o1.x = v10; o1.y = v11;
                *reinterpret_cast<float2*>(&C[(size_t)row0 * D_MODEL + col]) = o0;
                *reinterpret_cast<float2*>(&C[(size_t)(row0 + 8) * D_MODEL + col]) = o1;
            }
        }
    }
}

__global__ __launch_bounds__(256, 2) void qkv_gemm_kernel_b(
    const float* __restrict__ bq, const float* __restrict__ bk,
    const float* __restrict__ bv)
{
    const int z = blockIdx.z;
    const float* A = (z == 0) ? g_Xq : (z == 1) ? g_Xk : g_Xv;
    const float* W = (z == 0) ? g_Wqt : (z == 1) ? g_Wkt : g_Wvt;
    const float* b = (z == 0) ? bq : (z == 1) ? bk : bv;
    float*       C = (z == 0) ? g_Q : (z == 1) ? g_K : g_V;
    const float sc = (z == 0) ? 0.03125f : 1.0f;
    gemm_body<true>(A, W, b, C, sc);
}

__global__ __launch_bounds__(256, 2) void gemm_o_kernel(
    const float* __restrict__ bias, float* __restrict__ C)
{
    gemm_body<false>(g_O, g_Wot, bias, C, 1.0f);
}

// ---------------------------------------------------------------------------
// tf32 flash attention — exact R5 version (proven fastest: ~260us).
// KCH=64, Q in registers, 2-stage cp.async K/V, O stored as tf32 bits.
// ---------------------------------------------------------------------------
#define QTILE 128
#define KCH 64
#define KST 68
#define VST 72
#define ASM_K (64 * KST)
#define ASM_V (64 * VST)
#define KOFF_V (2 * ASM_K)
#define POFF  (2 * ASM_K + 2 * ASM_V)
#define ASM_P (QTILE * KST)
#define ATTN_SMEM ((POFF + ASM_P) * 4)   // 106496 bytes
#define NTC (SEQ / KCH)                  // 32

__global__ __launch_bounds__(256) void attn_kernel()
{
    extern __shared__ uint32_t smu[];
    const uint32_t su = (uint32_t)__cvta_generic_to_shared(smu);
    uint32_t* Psm = smu + POFF;

    const int tid  = threadIdx.x;
    const int warp = tid >> 5;
    const int lane = tid & 31;
    const int lr = lane >> 2;
    const int lc = lane & 3;
    const int wm = warp * 16;

    const int qblk = blockIdx.x;
    const int bh   = blockIdx.y;
    const int b = bh >> 4;
    const int h = bh & 15;
    const size_t baseRow = (size_t)b * SEQ;
    const int colOff = h * HEAD_DIM;

    auto issue_chunk = [&](int kt, int buf) {
#pragma unroll
        for (int i = 0; i < 4; i++) {
            const int idx = tid + 256 * i;
            const int r  = idx >> 4;
            const int d4 = (idx & 15) << 2;
            const size_t g = (baseRow + (size_t)kt * KCH + r) * D_MODEL + colOff + d4;
            cp16(su + (uint32_t)(buf * ASM_K + r * KST + d4) * 4, &g_K[g]);
            cp16(su + (uint32_t)(KOFF_V + buf * ASM_V + r * VST + d4) * 4, &g_V[g]);
        }
        cp_commit();
    };

    issue_chunk(0, 0);

#pragma unroll
    for (int i = 0; i < 8; i++) {
        const int idx = tid + 256 * i;
        const int r  = idx >> 4;
        const int d4 = (idx & 15) << 2;
        *reinterpret_cast<uint4*>(&Psm[r * KST + d4]) =
            *reinterpret_cast<const uint4*>(
                &g_Q[(baseRow + qblk * QTILE + r) * D_MODEL + colOff + d4]);
    }
    __syncthreads();

    uint32_t qf[8][4];
#pragma unroll
    for (int ks = 0; ks < 8; ks++) {
        const int k0 = ks * 8;
        qf[ks][0] = Psm[(wm + lr    ) * KST + k0 + lc    ];
        qf[ks][1] = Psm[(wm + lr + 8) * KST + k0 + lc    ];
        qf[ks][2] = Psm[(wm + lr    ) * KST + k0 + lc + 4];
        qf[ks][3] = Psm[(wm + lr + 8) * KST + k0 + lc + 4];
    }

    float oacc[8][4];
#pragma unroll
    for (int ni = 0; ni < 8; ni++)
#pragma unroll
        for (int r = 0; r < 4; r++) oacc[ni][r] = 0.0f;
    float m0 = -INFINITY, m1 = -INFINITY, l0 = 0.0f, l1 = 0.0f;

    for (int kt = 0; kt < NTC; kt++) {
        const int buf = kt & 1;
        if (kt + 1 < NTC) {
            issue_chunk(kt + 1, buf ^ 1);
            cp_wait<1>();
        } else {
            cp_wait<0>();
        }
        __syncthreads();

        const uint32_t* Ksm = smu + buf * ASM_K;
        const uint32_t* Vsm = smu + KOFF_V + buf * ASM_V;

        float sacc[8][4];
#pragma unroll
        for (int ni = 0; ni < 8; ni++)
#pragma unroll
            for (int r = 0; r < 4; r++) sacc[ni][r] = 0.0f;
#pragma unroll
        for (int ks = 0; ks < 8; ks++) {
            const int k0 = ks * 8;
#pragma unroll
            for (int ni = 0; ni < 8; ni++) {
                const uint32_t b0 = Ksm[(ni * 8 + lr) * KST + k0 + lc    ];
                const uint32_t b1 = Ksm[(ni * 8 + lr) * KST + k0 + lc + 4];
                mma_tf32(sacc[ni][0], sacc[ni][1], sacc[ni][2], sacc[ni][3],
                         qf[ks][0], qf[ks][1], qf[ks][2], qf[ks][3], b0, b1);
            }
        }

        float lm0 = -INFINITY, lm1 = -INFINITY;
#pragma unroll
        for (int ni = 0; ni < 8; ni++) {
            lm0 = fmaxf(lm0, fmaxf(sacc[ni][0], sacc[ni][1]));
            lm1 = fmaxf(lm1, fmaxf(sacc[ni][2], sacc[ni][3]));
        }
        lm0 = fmaxf(lm0, __shfl_xor_sync(0xffffffffu, lm0, 1));
        lm0 = fmaxf(lm0, __shfl_xor_sync(0xffffffffu, lm0, 2));
        lm1 = fmaxf(lm1, __shfl_xor_sync(0xffffffffu, lm1, 1));
        lm1 = fmaxf(lm1, __shfl_xor_sync(0xffffffffu, lm1, 2));
        const float mn0 = fmaxf(m0, lm0);
        const float mn1 = fmaxf(m1, lm1);
        const float a0 = __expf(m0 - mn0);
        const float a1 = __expf(m1 - mn1);
        m0 = mn0; m1 = mn1;
        float rs0 = 0.0f, rs1 = 0.0f;
#pragma unroll
        for (int ni = 0; ni < 8; ni++) {
            sacc[ni][0] = __expf(sacc[ni][0] - mn0);
            sacc[ni][1] = __expf(sacc[ni][1] - mn0);
            sacc[ni][2] = __expf(sacc[ni][2] - mn1);
            sacc[ni][3] = __expf(sacc[ni][3] - mn1);
            rs0 += sacc[ni][0] + sacc[ni][1];
            rs1 += sacc[ni][2] + sacc[ni][3];
        }
        rs0 += __shfl_xor_sync(0xffffffffu, rs0, 1);
        rs0 += __shfl_xor_sync(0xffffffffu, rs0, 2);
        rs1 += __shfl_xor_sync(0xffffffffu, rs1, 1);
        rs1 += __shfl_xor_sync(0xffffffffu, rs1, 2);
        l0 = l0 * a0 + rs0;
        l1 = l1 * a1 + rs1;
#pragma unroll
        for (int ni = 0; ni < 8; ni++) {
            oacc[ni][0] *= a0; oacc[ni][1] *= a0;
            oacc[ni][2] *= a1; oacc[ni][3] *= a1;
        }

#pragma unroll
        for (int ni = 0; ni < 8; ni++) {
            const int col = ni * 8 + lc * 2;
            uint2 p0, p1;
            p0.x = f2tf32(sacc[ni][0]); p0.y = f2tf32(sacc[ni][1]);
            p1.x = f2tf32(sacc[ni][2]); p1.y = f2tf32(sacc[ni][3]);
            *reinterpret_cast<uint2*>(&Psm[(wm + lr    ) * KST + col]) = p0;
            *reinterpret_cast<uint2*>(&Psm[(wm + lr + 8) * KST + col]) = p1;
        }
        __syncwarp();

#pragma unroll
        for (int ks = 0; ks < 8; ks++) {
            const int k0 = ks * 8;
            uint32_t af0 = Psm[(wm + lr    ) * KST + k0 + lc    ];
            uint32_t af1 = Psm[(wm + lr + 8) * KST + k0 + lc    ];
            uint32_t af2 = Psm[(wm + lr    ) * KST + k0 + lc + 4];
            uint32_t af3 = Psm[(wm + lr + 8) * KST + k0 + lc + 4];
#pragma unroll
            for (int ni = 0; ni < 8; ni++) {
                const uint32_t b0 = Vsm[(k0 + lc    ) * VST + ni * 8 + lr];
                const uint32_t b1 = Vsm[(k0 + lc + 4) * VST + ni * 8 + lr];
                mma_tf32(oacc[ni][0], oacc[ni][1], oacc[ni][2], oacc[ni][3],
                         af0, af1, af2, af3, b0, b1);
            }
        }
        __syncthreads();
    }

    const float inv0 = 1.0f / l0;
    const float inv1 = 1.0f / l1;
    const size_t r0 = baseRow + qblk * QTILE + wm + lr;
    uint32_t* Og = reinterpret_cast<uint32_t*>(g_O);
#pragma unroll
    for (int ni = 0; ni < 8; ni++) {
        const int col = colOff + ni * 8 + lc * 2;
        uint2 o0, o1;
        o0.x = f2tf32(oacc[ni][0] * inv0); o0.y = f2tf32(oacc[ni][1] * inv0);
        o1.x = f2tf32(oacc[ni][2] * inv1); o1.y = f2tf32(oacc[ni][3] * inv1);
        *reinterpret_cast<uint2*>(&Og[r0 * D_MODEL + col]) = o0;
        *reinterpret_cast<uint2*>(&Og[(r0 + 8) * D_MODEL + col]) = o1;
    }
}

// ---------------------------------------------------------------------------
extern "C" void kernel_launch(void* const* d_in, const int* in_sizes, int n_in,
                              void* d_out, int out_size)
{
    const float* queries = (const float*)d_in[0];
    const float* keys    = (const float*)d_in[1];
    const float* values  = (const float*)d_in[2];
    const float* Wq = (const float*)d_in[3];
    const float* bq = (const float*)d_in[4];
    const float* Wk = (const float*)d_in[5];
    const float* bk = (const float*)d_in[6];
    const float* Wv = (const float*)d_in[7];
    const float* bv = (const float*)d_in[8];
    const float* Wo = (const float*)d_in[9];
    const float* bo = (const float*)d_in[10];
    float* out = (float*)d_out;

    prep_kernel<<<dim3(MTOT * D_MODEL / 4 / 256, 7), 256>>>(
        queries, keys, values, Wq, Wk, Wv, Wo);

    cudaFuncSetAttribute(qkv_gemm_kernel_b,
                         cudaFuncAttributeMaxDynamicSharedMemorySize, GEMM_SMEM);
    cudaFuncSetAttribute(gemm_o_kernel,
                         cudaFuncAttributeMaxDynamicSharedMemorySize, GEMM_SMEM);
    cudaFuncSetAttribute(attn_kernel,
                         cudaFuncAttributeMaxDynamicSharedMemorySize, ATTN_SMEM);

    qkv_gemm_kernel_b<<<dim3(D_MODEL / BN, MTOT / BM, 3), 256, GEMM_SMEM>>>(
        bq, bk, bv);

    attn_kernel<<<dim3(SEQ / QTILE, BATCH * HEADS), 256, ATTN_SMEM>>>();

    gemm_o_kernel<<<dim3(D_MODEL / BN, MTOT / BM), 256, GEMM_SMEM>>>(bo, out);
}